// round 13
// baseline (speedup 1.0000x reference)
#include <cuda_runtime.h>
#include <mma.h>
#include <math.h>
#include <cstdint>
#include <cuda_fp16.h>

using namespace nvcuda;

#define Bsz 512
#define Lsz 128
#define Dsz 512
#define Hn  8
#define HDsz 64
#define LN_EPS 1e-5f

// Scratch (static device globals -- allocation-guard safe)
__device__ __half g_qkv[Bsz * Lsz * 3 * Dsz];
__device__ __half g_oh[Bsz * Lsz * Dsz];
__device__ __half g_xh[Bsz * Lsz * Dsz];
__device__ __half g_wih[3 * Dsz * Dsz];
__device__ __half g_woh[Dsz * Dsz];

__device__ __forceinline__ void cp16(uint32_t d, const void* s) {
    asm volatile("cp.async.cg.shared.global [%0], [%1], 16;" :: "r"(d), "l"(s));
}

// ---------------------------------------------------------------------------
// fp32 -> fp16 conversion for x, in_w, out_w in ONE launch.
// ---------------------------------------------------------------------------
__global__ void f2h_multi(const float* __restrict__ x,   __half* __restrict__ xh,
                          const float* __restrict__ w1,  __half* __restrict__ w1h,
                          const float* __restrict__ w2,  __half* __restrict__ w2h)
{
    const int bid = blockIdx.x;
    const float* in; __half* out; int base;
    if (bid < 16384)      { in = x;  out = xh;  base = bid; }
    else if (bid < 16768) { in = w1; out = w1h; base = bid - 16384; }
    else                  { in = w2; out = w2h; base = bid - 16768; }
    const int i = base * 2048 + threadIdx.x * 8;
    float4 a = *(const float4*)(in + i);
    float4 b = *(const float4*)(in + i + 4);
    __half2 h0 = __floats2half2_rn(a.x, a.y);
    __half2 h1 = __floats2half2_rn(a.z, a.w);
    __half2 h2 = __floats2half2_rn(b.x, b.y);
    __half2 h3 = __floats2half2_rn(b.z, b.w);
    uint4 pk;
    pk.x = *(uint32_t*)&h0; pk.y = *(uint32_t*)&h1;
    pk.z = *(uint32_t*)&h2; pk.w = *(uint32_t*)&h3;
    *(uint4*)(out + i) = pk;
}

// ---------------------------------------------------------------------------
// QKV GEMM: C = A @ W^T + bias (fp16 out).
// BM=BN=128, BK=64. 256 thr (8 warps), warp tile 32x64.
// 2-stage cp.async, SINGLE sync per iter, 3 CTAs/SM (24 warps/SM).
// Per iter: wait(tile ks) -> sync -> issue load(ks+1) -> compute(ks).
// WAR safe: buf[(ks+1)&1] last read by compute(ks-1), which all warps
// completed before this iteration's sync.
// ---------------------------------------------------------------------------
#define LDTh 72
#define STG_HALFS (256 * LDTh)
#define STG_BYTES (STG_HALFS * 2)             // 36864 B
#define GEMM_SMEM (STG_BYTES * 2)             // 73728 B

__global__ void __launch_bounds__(256, 3)
gemm_qkv(const __half* __restrict__ A, const __half* __restrict__ W,
         const float* __restrict__ bias, __half* __restrict__ C, int M, int N, int K)
{
    constexpr int LDO = 132;
    extern __shared__ __half sh[];
    float* sf = (float*)sh;

    const int t   = threadIdx.x;
    const int wid = t >> 5;
    const int bm  = blockIdx.y * 128;
    const int bn  = blockIdx.x * 128;
    const int wr  = wid & 3;
    const int wc  = wid >> 2;

    wmma::fragment<wmma::accumulator, 16, 16, 16, float> acc[2][4];
    #pragma unroll
    for (int i = 0; i < 2; i++)
        #pragma unroll
        for (int j = 0; j < 4; j++) wmma::fill_fragment(acc[i][j], 0.0f);

    const uint32_t sbase = (uint32_t)__cvta_generic_to_shared(sh);

    auto load_tile = [&](int s, int k0) {
        const uint32_t base = sbase + s * STG_BYTES;
        #pragma unroll
        for (int i = 0; i < 4; i++) {
            const int j = i * 256 + t;
            const int row = j >> 3, c = j & 7;
            cp16(base + row * 144 + c * 16, A + (size_t)(bm + row) * K + k0 + c * 8);
        }
        const uint32_t bb = base + 128 * 144;
        #pragma unroll
        for (int i = 0; i < 4; i++) {
            const int j = i * 256 + t;
            const int row = j >> 3, c = j & 7;
            cp16(bb + row * 144 + c * 16, W + (size_t)(bn + row) * K + k0 + c * 8);
        }
        asm volatile("cp.async.commit_group;");
    };

    const int NK = K / 64;   // 8
    load_tile(0, 0);

    for (int ks = 0; ks < NK; ks++) {
        asm volatile("cp.async.wait_group 0;");   // tile ks landed
        __syncthreads();                          // visible to all; prev reads done
        if (ks + 1 < NK) load_tile((ks + 1) & 1, (ks + 1) * 64);  // overlaps compute

        const __half* a = sh + (ks & 1) * STG_HALFS;
        const __half* w = a + 128 * LDTh;
        #pragma unroll
        for (int kk = 0; kk < 64; kk += 16) {
            wmma::fragment<wmma::matrix_a, 16, 16, 16, __half, wmma::row_major> af[2];
            wmma::load_matrix_sync(af[0], a + (wr * 32) * LDTh + kk, LDTh);
            wmma::load_matrix_sync(af[1], a + (wr * 32 + 16) * LDTh + kk, LDTh);
            #pragma unroll
            for (int j = 0; j < 4; j++) {
                wmma::fragment<wmma::matrix_b, 16, 16, 16, __half, wmma::col_major> bf;
                wmma::load_matrix_sync(bf, w + (wc * 64 + j * 16) * LDTh + kk, LDTh);
                wmma::mma_sync(acc[0][j], af[0], bf, acc[0][j]);
                wmma::mma_sync(acc[1][j], af[1], bf, acc[1][j]);
            }
        }
    }
    __syncthreads();

    #pragma unroll
    for (int i = 0; i < 2; i++)
        #pragma unroll
        for (int j = 0; j < 4; j++)
            wmma::store_matrix_sync(sf + (wr * 32 + i * 16) * LDO + wc * 64 + j * 16,
                                    acc[i][j], LDO, wmma::mem_row_major);
    __syncthreads();

    const int r  = t >> 1;
    const int cb = (t & 1) * 64;
    const size_t grow = (size_t)(bm + r) * N + bn;
    #pragma unroll
    for (int u = 0; u < 16; u++) {
        const int c = cb + u * 4;
        float4 v = *(float4*)&sf[r * LDO + c];
        v.x += bias[bn + c];     v.y += bias[bn + c + 1];
        v.z += bias[bn + c + 2]; v.w += bias[bn + c + 3];
        __half2 h0 = __floats2half2_rn(v.x, v.y);
        __half2 h1 = __floats2half2_rn(v.z, v.w);
        uint2 pk; pk.x = *(uint32_t*)&h0; pk.y = *(uint32_t*)&h1;
        *(uint2*)((__half*)C + grow + c) = pk;
    }
}

// ---------------------------------------------------------------------------
// Fused out_proj + bias + residual + LayerNorm (R8 3-stage).
// BM=64, BN=512, BK=32, 512 thr, grid = 1024.
// ---------------------------------------------------------------------------
#define LDTb 40
#define OP_B_BYTES (512 * 80)
#define OP_A_BYTES (64 * 80)
#define OP_STG (OP_B_BYTES + OP_A_BYTES)
#define OPLN_SMEM (OP_STG * 3)
#define LDOo 516

__global__ void __launch_bounds__(512, 1)
outproj_ln(const __half* __restrict__ A, const __half* __restrict__ W,
           const float* __restrict__ out_b, const float* __restrict__ x,
           const float* __restrict__ lnw, const float* __restrict__ lnb,
           float* __restrict__ out)
{
    extern __shared__ __half sh[];
    float* sf = (float*)sh;

    const int t   = threadIdx.x;
    const int wid = t >> 5;
    const int bm  = blockIdx.x * 64;
    const int wr  = wid & 1;
    const int wc  = wid >> 1;

    wmma::fragment<wmma::accumulator, 16, 16, 16, float> acc[2][4];
    #pragma unroll
    for (int i = 0; i < 2; i++)
        #pragma unroll
        for (int j = 0; j < 4; j++) wmma::fill_fragment(acc[i][j], 0.0f);

    const uint32_t sbase = (uint32_t)__cvta_generic_to_shared(sh);

    auto load_tile = [&](int s, int k0) {
        const uint32_t base = sbase + s * OP_STG;
        #pragma unroll
        for (int i = 0; i < 4; i++) {
            const int j = i * 512 + t;
            const int row = j >> 2, c = j & 3;
            cp16(base + row * 80 + c * 16, W + (size_t)row * Dsz + k0 + c * 8);
        }
        if (t < 256) {
            const int row = t >> 2, c = t & 3;
            cp16(base + OP_B_BYTES + row * 80 + c * 16,
                 A + (size_t)(bm + row) * Dsz + k0 + c * 8);
        }
    };

    const int NK = Dsz / 32;
    load_tile(0, 0);  asm volatile("cp.async.commit_group;");
    load_tile(1, 32); asm volatile("cp.async.commit_group;");

    for (int ks = 0; ks < NK; ks++) {
        asm volatile("cp.async.wait_group 1;");
        __syncthreads();
        if (ks + 2 < NK) load_tile((ks + 2) % 3, (ks + 2) * 32);
        asm volatile("cp.async.commit_group;");

        const __half* bsm = sh + (ks % 3) * (OP_STG / 2);
        const __half* asm_ = bsm + OP_B_BYTES / 2;
        #pragma unroll
        for (int kk = 0; kk < 32; kk += 16) {
            wmma::fragment<wmma::matrix_a, 16, 16, 16, __half, wmma::row_major> af[2];
            wmma::load_matrix_sync(af[0], asm_ + (wr * 32) * LDTb + kk, LDTb);
            wmma::load_matrix_sync(af[1], asm_ + (wr * 32 + 16) * LDTb + kk, LDTb);
            #pragma unroll
            for (int j = 0; j < 4; j++) {
                wmma::fragment<wmma::matrix_b, 16, 16, 16, __half, wmma::col_major> bf;
                wmma::load_matrix_sync(bf, bsm + (wc * 64 + j * 16) * LDTb + kk, LDTb);
                wmma::mma_sync(acc[0][j], af[0], bf, acc[0][j]);
                wmma::mma_sync(acc[1][j], af[1], bf, acc[1][j]);
            }
        }
    }
    __syncthreads();

    #pragma unroll
    for (int i = 0; i < 2; i++)
        #pragma unroll
        for (int j = 0; j < 4; j++)
            wmma::store_matrix_sync(sf + (wr * 32 + i * 16) * LDOo + wc * 64 + j * 16,
                                    acc[i][j], LDOo, wmma::mem_row_major);
    __syncthreads();

    {
        const int row = t >> 3;
        const int l8  = t & 7;
        const int gr  = bm + row;
        float v[64];
        float s = 0.0f, s2 = 0.0f;
        #pragma unroll
        for (int u = 0; u < 16; u++) {
            const int c = l8 * 4 + u * 32;
            float4 a4 = *(float4*)&sf[row * LDOo + c];
            float4 b4 = *(const float4*)&out_b[c];
            float4 x4 = *(const float4*)&x[(size_t)gr * Dsz + c];
            a4.x += b4.x + x4.x; a4.y += b4.y + x4.y;
            a4.z += b4.z + x4.z; a4.w += b4.w + x4.w;
            v[u*4+0] = a4.x; v[u*4+1] = a4.y; v[u*4+2] = a4.z; v[u*4+3] = a4.w;
            s  += a4.x + a4.y + a4.z + a4.w;
            s2 += a4.x*a4.x + a4.y*a4.y + a4.z*a4.z + a4.w*a4.w;
        }
        #pragma unroll
        for (int o = 1; o < 8; o <<= 1) {
            s  += __shfl_xor_sync(0xffffffffu, s,  o);
            s2 += __shfl_xor_sync(0xffffffffu, s2, o);
        }
        const float mu  = s * (1.0f / Dsz);
        const float var = s2 * (1.0f / Dsz) - mu * mu;
        const float inv = rsqrtf(var + LN_EPS);
        #pragma unroll
        for (int u = 0; u < 16; u++) {
            const int c = l8 * 4 + u * 32;
            float4 w4 = *(const float4*)&lnw[c];
            float4 b4 = *(const float4*)&lnb[c];
            float4 r;
            r.x = (v[u*4+0] - mu) * inv * w4.x + b4.x;
            r.y = (v[u*4+1] - mu) * inv * w4.y + b4.y;
            r.z = (v[u*4+2] - mu) * inv * w4.z + b4.z;
            r.w = (v[u*4+3] - mu) * inv * w4.w + b4.w;
            *(float4*)&out[(size_t)gr * Dsz + c] = r;
        }
    }
}

// ---------------------------------------------------------------------------
// Attention: one block per (b, h). 256 threads (8 warps). 2 CTAs/SM.
// ---------------------------------------------------------------------------
#define ATTN_DYN (2 * 128 * 72 * 2 + 128 * 132 * 4)

__global__ void __launch_bounds__(256, 2)
attn_kernel(const __half* __restrict__ qkv,
            const float* __restrict__ corr,
            const int*   __restrict__ mask,
            const float* __restrict__ bscale,
            __half* __restrict__ og)
{
    extern __shared__ __half smh[];
    __half* sQ = smh;
    __half* sK = smh + 128 * 72;
    float*  sS = (float*)(smh + 2 * 128 * 72);
    __half* sP = (__half*)sS;
    __half* sV = sK;
    __shared__ __align__(16) float sB[128];

    const int bh = blockIdx.x;
    const int b  = bh >> 3;
    const int h  = bh & 7;
    const int t  = threadIdx.x;
    const int wid  = t >> 5;

    const uint32_t qb = (uint32_t)__cvta_generic_to_shared(sQ);
    const uint32_t kb = (uint32_t)__cvta_generic_to_shared(sK);
    const __half* src = qkv + (size_t)(b * Lsz) * (3 * Dsz) + h * HDsz;

    #pragma unroll
    for (int i = 0; i < 4; i++) {
        const int j = i * 256 + t;
        const int row = j >> 3, c = j & 7;
        cp16(qb + row * 144 + c * 16, src + (size_t)row * 1536 + c * 8);
        cp16(kb + row * 144 + c * 16, src + (size_t)row * 1536 + 512 + c * 8);
    }
    asm volatile("cp.async.commit_group;");
    if (t < 128) {
        const float bsc = bscale[0];
        sB[t] = mask[b * Lsz + t] ? -1e30f : bsc * corr[b * Lsz + t];
    }
    asm volatile("cp.async.wait_group 0;");
    __syncthreads();

    {
        const int wr = wid & 3, wc = wid >> 2;
        const int r0 = wr * 32, c0 = wc * 64;
        wmma::fragment<wmma::accumulator, 16, 16, 16, float> acc[2][4];
        #pragma unroll
        for (int i = 0; i < 2; i++)
            #pragma unroll
            for (int j = 0; j < 4; j++) wmma::fill_fragment(acc[i][j], 0.0f);

        #pragma unroll
        for (int kk = 0; kk < 64; kk += 16) {
            wmma::fragment<wmma::matrix_a, 16, 16, 16, __half, wmma::row_major> af[2];
            wmma::load_matrix_sync(af[0], &sQ[(r0 +  0) * 72 + kk], 72);
            wmma::load_matrix_sync(af[1], &sQ[(r0 + 16) * 72 + kk], 72);
            #pragma unroll
            for (int j = 0; j < 4; j++) {
                wmma::fragment<wmma::matrix_b, 16, 16, 16, __half, wmma::col_major> bf;
                wmma::load_matrix_sync(bf, &sK[(c0 + j * 16) * 72 + kk], 72);
                wmma::mma_sync(acc[0][j], af[0], bf, acc[0][j]);
                wmma::mma_sync(acc[1][j], af[1], bf, acc[1][j]);
            }
        }
        #pragma unroll
        for (int i = 0; i < 2; i++)
            #pragma unroll
            for (int j = 0; j < 4; j++)
                wmma::store_matrix_sync(&sS[(r0 + i * 16) * 132 + c0 + j * 16],
                                        acc[i][j], 132, wmma::mem_row_major);
    }
    __syncthreads();

    #pragma unroll
    for (int i = 0; i < 4; i++) {
        const int j = i * 256 + t;
        const int row = j >> 3, c = j & 7;
        cp16(kb + row * 144 + c * 16, src + (size_t)row * 1536 + 1024 + c * 8);
    }
    asm volatile("cp.async.commit_group;");

    {
        const int r   = t >> 1;
        const int seg = t & 1;
        const float* srow = &sS[r * 132 + seg * 64];
        const float* brow = &sB[seg * 64];
        float v[64];
        float m = -1e30f;
        #pragma unroll
        for (int u = 0; u < 16; u++) {
            float4 s4 = *(const float4*)(srow + u * 4);
            float4 b4 = *(const float4*)(brow + u * 4);
            v[u*4+0] = fmaf(s4.x, 0.125f, b4.x);
            v[u*4+1] = fmaf(s4.y, 0.125f, b4.y);
            v[u*4+2] = fmaf(s4.z, 0.125f, b4.z);
            v[u*4+3] = fmaf(s4.w, 0.125f, b4.w);
            m = fmaxf(m, fmaxf(fmaxf(v[u*4], v[u*4+1]), fmaxf(v[u*4+2], v[u*4+3])));
        }
        m = fmaxf(m, __shfl_xor_sync(0xffffffffu, m, 1));
        float s = 0.0f;
        #pragma unroll
        for (int u = 0; u < 64; u++) { v[u] = __expf(v[u] - m); s += v[u]; }
        s += __shfl_xor_sync(0xffffffffu, s, 1);
        const float inv = 1.0f / s;
        __half* prow = sP + r * 264 + seg * 64;
        #pragma unroll
        for (int u = 0; u < 8; u++) {
            __half2 p0 = __floats2half2_rn(v[u*8+0] * inv, v[u*8+1] * inv);
            __half2 p1 = __floats2half2_rn(v[u*8+2] * inv, v[u*8+3] * inv);
            __half2 p2 = __floats2half2_rn(v[u*8+4] * inv, v[u*8+5] * inv);
            __half2 p3 = __floats2half2_rn(v[u*8+6] * inv, v[u*8+7] * inv);
            uint4 pk;
            pk.x = *(uint32_t*)&p0; pk.y = *(uint32_t*)&p1;
            pk.z = *(uint32_t*)&p2; pk.w = *(uint32_t*)&p3;
            *(uint4*)(prow + u * 8) = pk;
        }
    }
    asm volatile("cp.async.wait_group 0;");
    __syncthreads();

    {
        const int r0 = wid * 16;
        wmma::fragment<wmma::accumulator, 16, 16, 16, float> acc[4];
        #pragma unroll
        for (int c = 0; c < 4; c++) wmma::fill_fragment(acc[c], 0.0f);

        #pragma unroll
        for (int j = 0; j < 128; j += 16) {
            wmma::fragment<wmma::matrix_a, 16, 16, 16, __half, wmma::row_major> af;
            wmma::load_matrix_sync(af, &sP[r0 * 264 + j], 264);
            #pragma unroll
            for (int c = 0; c < 4; c++) {
                wmma::fragment<wmma::matrix_b, 16, 16, 16, __half, wmma::row_major> bf;
                wmma::load_matrix_sync(bf, &sV[j * 72 + c * 16], 72);
                wmma::mma_sync(acc[c], af, bf, acc[c]);
            }
        }
        #pragma unroll
        for (int c = 0; c < 4; c++)
            wmma::store_matrix_sync(&sS[r0 * 132 + c * 16], acc[c], 132, wmma::mem_row_major);
    }
    __syncthreads();

    {
        const int r   = t >> 1;
        const int seg = (t & 1) * 32;
        __half* dst = og + (size_t)(b * Lsz + r) * Dsz + h * HDsz + seg;
        const float* srcO = &sS[r * 132 + seg];
        #pragma unroll
        for (int u = 0; u < 4; u++) {
            float4 a = *(const float4*)(srcO + u * 8);
            float4 c = *(const float4*)(srcO + u * 8 + 4);
            __half2 h0 = __floats2half2_rn(a.x, a.y);
            __half2 h1 = __floats2half2_rn(a.z, a.w);
            __half2 h2 = __floats2half2_rn(c.x, c.y);
            __half2 h3 = __floats2half2_rn(c.z, c.w);
            uint4 pk;
            pk.x = *(uint32_t*)&h0; pk.y = *(uint32_t*)&h1;
            pk.z = *(uint32_t*)&h2; pk.w = *(uint32_t*)&h3;
            *(uint4*)(dst + u * 8) = pk;
        }
    }
}

// ---------------------------------------------------------------------------
extern "C" void kernel_launch(void* const* d_in, const int* in_sizes, int n_in,
                              void* d_out, int out_size)
{
    const float* x      = (const float*)d_in[0];
    const float* corr   = (const float*)d_in[1];
    const int*   mask   = (const int*)  d_in[2];
    const float* in_w   = (const float*)d_in[3];
    const float* in_b   = (const float*)d_in[4];
    const float* out_w  = (const float*)d_in[5];
    const float* out_b  = (const float*)d_in[6];
    const float* ln_w   = (const float*)d_in[7];
    const float* ln_b   = (const float*)d_in[8];
    const float* bscale = (const float*)d_in[9];
    float* out = (float*)d_out;

    __half *qkv, *oh, *xh, *wih, *woh;
    cudaGetSymbolAddress((void**)&qkv, g_qkv);
    cudaGetSymbolAddress((void**)&oh,  g_oh);
    cudaGetSymbolAddress((void**)&xh,  g_xh);
    cudaGetSymbolAddress((void**)&wih, g_wih);
    cudaGetSymbolAddress((void**)&woh, g_woh);

    const int M = Bsz * Lsz;   // 65536

    cudaFuncSetAttribute((void*)gemm_qkv,    cudaFuncAttributeMaxDynamicSharedMemorySize, GEMM_SMEM);
    cudaFuncSetAttribute((void*)outproj_ln,  cudaFuncAttributeMaxDynamicSharedMemorySize, OPLN_SMEM);
    cudaFuncSetAttribute((void*)attn_kernel, cudaFuncAttributeMaxDynamicSharedMemorySize, ATTN_DYN);

    // 0) fp32 -> fp16 conversions (one launch)
    f2h_multi<<<16896, 256>>>(x, xh, in_w, wih, out_w, woh);

    // 1) QKV projection -> fp16 qkv (2-stage single-sync, 3 CTAs/SM)
    gemm_qkv<<<dim3(3 * Dsz / 128, M / 128), 256, GEMM_SMEM>>>(
        xh, wih, in_b, qkv, M, 3 * Dsz, Dsz);

    // 2) Attention per (b, h)
    attn_kernel<<<Bsz * Hn, 256, ATTN_DYN>>>(qkv, corr, mask, bscale, oh);

    // 3) out_proj + bias + residual + LayerNorm -> out
    outproj_ln<<<M / 64, 512, OPLN_SMEM>>>(oh, woh, out_b, x, ln_w, ln_b, out);
}

// round 14
// speedup vs baseline: 1.3107x; 1.3107x over previous
#include <cuda_runtime.h>
#include <mma.h>
#include <math.h>
#include <cstdint>
#include <cuda_fp16.h>

using namespace nvcuda;

#define Bsz 512
#define Lsz 128
#define Dsz 512
#define Hn  8
#define HDsz 64
#define LN_EPS 1e-5f

// Scratch (static device globals -- allocation-guard safe)
__device__ __half g_qkv[Bsz * Lsz * 3 * Dsz];
__device__ __half g_oh[Bsz * Lsz * Dsz];
__device__ __half g_xh[Bsz * Lsz * Dsz];
__device__ __half g_wih[3 * Dsz * Dsz];
__device__ __half g_woh[Dsz * Dsz];

__device__ __forceinline__ void cp16(uint32_t d, const void* s) {
    asm volatile("cp.async.cg.shared.global [%0], [%1], 16;" :: "r"(d), "l"(s));
}

// ---------------------------------------------------------------------------
// fp32 -> fp16 conversion for x, in_w, out_w in ONE launch.
// ---------------------------------------------------------------------------
__global__ void f2h_multi(const float* __restrict__ x,   __half* __restrict__ xh,
                          const float* __restrict__ w1,  __half* __restrict__ w1h,
                          const float* __restrict__ w2,  __half* __restrict__ w2h)
{
    const int bid = blockIdx.x;
    const float* in; __half* out; int base;
    if (bid < 16384)      { in = x;  out = xh;  base = bid; }
    else if (bid < 16768) { in = w1; out = w1h; base = bid - 16384; }
    else                  { in = w2; out = w2h; base = bid - 16768; }
    const int i = base * 2048 + threadIdx.x * 8;
    float4 a = *(const float4*)(in + i);
    float4 b = *(const float4*)(in + i + 4);
    __half2 h0 = __floats2half2_rn(a.x, a.y);
    __half2 h1 = __floats2half2_rn(a.z, a.w);
    __half2 h2 = __floats2half2_rn(b.x, b.y);
    __half2 h3 = __floats2half2_rn(b.z, b.w);
    uint4 pk;
    pk.x = *(uint32_t*)&h0; pk.y = *(uint32_t*)&h1;
    pk.z = *(uint32_t*)&h2; pk.w = *(uint32_t*)&h3;
    *(uint4*)(out + i) = pk;
}

// ---------------------------------------------------------------------------
// QKV GEMM (R8 winner): C = A @ W^T + bias (fp16 out).
// BM=BN=128, BK=64. 256 thr (8 warps), warp tile 32x64. 3-stage, 2 CTAs/SM.
// Loads for tile ks+2 issued BEFORE compute of tile ks.
// ---------------------------------------------------------------------------
#define LDTh 72
#define STG_HALFS (256 * LDTh)
#define STG_BYTES (STG_HALFS * 2)             // 36864 B
#define GEMM_SMEM (STG_BYTES * 3)             // 110592 B

__global__ void __launch_bounds__(256, 2)
gemm_qkv(const __half* __restrict__ A, const __half* __restrict__ W,
         const float* __restrict__ bias, __half* __restrict__ C, int M, int N, int K)
{
    constexpr int LDO = 132;
    extern __shared__ __half sh[];
    float* sf = (float*)sh;

    const int t   = threadIdx.x;
    const int wid = t >> 5;
    const int bm  = blockIdx.y * 128;
    const int bn  = blockIdx.x * 128;
    const int wr  = wid & 3;
    const int wc  = wid >> 2;

    wmma::fragment<wmma::accumulator, 16, 16, 16, float> acc[2][4];
    #pragma unroll
    for (int i = 0; i < 2; i++)
        #pragma unroll
        for (int j = 0; j < 4; j++) wmma::fill_fragment(acc[i][j], 0.0f);

    const uint32_t sbase = (uint32_t)__cvta_generic_to_shared(sh);

    auto load_tile = [&](int s, int k0) {
        const uint32_t base = sbase + s * STG_BYTES;
        #pragma unroll
        for (int i = 0; i < 4; i++) {
            const int j = i * 256 + t;
            const int row = j >> 3, c = j & 7;
            cp16(base + row * 144 + c * 16, A + (size_t)(bm + row) * K + k0 + c * 8);
        }
        const uint32_t bb = base + 128 * 144;
        #pragma unroll
        for (int i = 0; i < 4; i++) {
            const int j = i * 256 + t;
            const int row = j >> 3, c = j & 7;
            cp16(bb + row * 144 + c * 16, W + (size_t)(bn + row) * K + k0 + c * 8);
        }
    };

    const int NK = K / 64;   // 8
    load_tile(0, 0);  asm volatile("cp.async.commit_group;");
    load_tile(1, 64); asm volatile("cp.async.commit_group;");

    for (int ks = 0; ks < NK; ks++) {
        asm volatile("cp.async.wait_group 1;");
        __syncthreads();
        // issue next-stage loads BEFORE compute for max overlap
        if (ks + 2 < NK) load_tile((ks + 2) % 3, (ks + 2) * 64);
        asm volatile("cp.async.commit_group;");

        const __half* a = sh + (ks % 3) * STG_HALFS;
        const __half* w = a + 128 * LDTh;
        #pragma unroll
        for (int kk = 0; kk < 64; kk += 16) {
            wmma::fragment<wmma::matrix_a, 16, 16, 16, __half, wmma::row_major> af[2];
            wmma::load_matrix_sync(af[0], a + (wr * 32) * LDTh + kk, LDTh);
            wmma::load_matrix_sync(af[1], a + (wr * 32 + 16) * LDTh + kk, LDTh);
            #pragma unroll
            for (int j = 0; j < 4; j++) {
                wmma::fragment<wmma::matrix_b, 16, 16, 16, __half, wmma::col_major> bf;
                wmma::load_matrix_sync(bf, w + (wc * 64 + j * 16) * LDTh + kk, LDTh);
                wmma::mma_sync(acc[0][j], af[0], bf, acc[0][j]);
                wmma::mma_sync(acc[1][j], af[1], bf, acc[1][j]);
            }
        }
    }
    __syncthreads();

    #pragma unroll
    for (int i = 0; i < 2; i++)
        #pragma unroll
        for (int j = 0; j < 4; j++)
            wmma::store_matrix_sync(sf + (wr * 32 + i * 16) * LDO + wc * 64 + j * 16,
                                    acc[i][j], LDO, wmma::mem_row_major);
    __syncthreads();

    const int r  = t >> 1;
    const int cb = (t & 1) * 64;
    const size_t grow = (size_t)(bm + r) * N + bn;
    #pragma unroll
    for (int u = 0; u < 16; u++) {
        const int c = cb + u * 4;
        float4 v = *(float4*)&sf[r * LDO + c];
        v.x += bias[bn + c];     v.y += bias[bn + c + 1];
        v.z += bias[bn + c + 2]; v.w += bias[bn + c + 3];
        __half2 h0 = __floats2half2_rn(v.x, v.y);
        __half2 h1 = __floats2half2_rn(v.z, v.w);
        uint2 pk; pk.x = *(uint32_t*)&h0; pk.y = *(uint32_t*)&h1;
        *(uint2*)((__half*)C + grow + c) = pk;
    }
}

// ---------------------------------------------------------------------------
// Fused out_proj + bias + residual + LayerNorm (R8 3-stage).
// BM=64, BN=512, BK=32, 512 thr, grid = 1024.
// ---------------------------------------------------------------------------
#define LDTb 40
#define OP_B_BYTES (512 * 80)
#define OP_A_BYTES (64 * 80)
#define OP_STG (OP_B_BYTES + OP_A_BYTES)
#define OPLN_SMEM (OP_STG * 3)
#define LDOo 516

__global__ void __launch_bounds__(512, 1)
outproj_ln(const __half* __restrict__ A, const __half* __restrict__ W,
           const float* __restrict__ out_b, const float* __restrict__ x,
           const float* __restrict__ lnw, const float* __restrict__ lnb,
           float* __restrict__ out)
{
    extern __shared__ __half sh[];
    float* sf = (float*)sh;

    const int t   = threadIdx.x;
    const int wid = t >> 5;
    const int bm  = blockIdx.x * 64;
    const int wr  = wid & 1;
    const int wc  = wid >> 1;

    wmma::fragment<wmma::accumulator, 16, 16, 16, float> acc[2][4];
    #pragma unroll
    for (int i = 0; i < 2; i++)
        #pragma unroll
        for (int j = 0; j < 4; j++) wmma::fill_fragment(acc[i][j], 0.0f);

    const uint32_t sbase = (uint32_t)__cvta_generic_to_shared(sh);

    auto load_tile = [&](int s, int k0) {
        const uint32_t base = sbase + s * OP_STG;
        #pragma unroll
        for (int i = 0; i < 4; i++) {
            const int j = i * 512 + t;
            const int row = j >> 2, c = j & 3;
            cp16(base + row * 80 + c * 16, W + (size_t)row * Dsz + k0 + c * 8);
        }
        if (t < 256) {
            const int row = t >> 2, c = t & 3;
            cp16(base + OP_B_BYTES + row * 80 + c * 16,
                 A + (size_t)(bm + row) * Dsz + k0 + c * 8);
        }
    };

    const int NK = Dsz / 32;
    load_tile(0, 0);  asm volatile("cp.async.commit_group;");
    load_tile(1, 32); asm volatile("cp.async.commit_group;");

    for (int ks = 0; ks < NK; ks++) {
        asm volatile("cp.async.wait_group 1;");
        __syncthreads();
        if (ks + 2 < NK) load_tile((ks + 2) % 3, (ks + 2) * 32);
        asm volatile("cp.async.commit_group;");

        const __half* bsm = sh + (ks % 3) * (OP_STG / 2);
        const __half* asm_ = bsm + OP_B_BYTES / 2;
        #pragma unroll
        for (int kk = 0; kk < 32; kk += 16) {
            wmma::fragment<wmma::matrix_a, 16, 16, 16, __half, wmma::row_major> af[2];
            wmma::load_matrix_sync(af[0], asm_ + (wr * 32) * LDTb + kk, LDTb);
            wmma::load_matrix_sync(af[1], asm_ + (wr * 32 + 16) * LDTb + kk, LDTb);
            #pragma unroll
            for (int j = 0; j < 4; j++) {
                wmma::fragment<wmma::matrix_b, 16, 16, 16, __half, wmma::col_major> bf;
                wmma::load_matrix_sync(bf, bsm + (wc * 64 + j * 16) * LDTb + kk, LDTb);
                wmma::mma_sync(acc[0][j], af[0], bf, acc[0][j]);
                wmma::mma_sync(acc[1][j], af[1], bf, acc[1][j]);
            }
        }
    }
    __syncthreads();

    #pragma unroll
    for (int i = 0; i < 2; i++)
        #pragma unroll
        for (int j = 0; j < 4; j++)
            wmma::store_matrix_sync(sf + (wr * 32 + i * 16) * LDOo + wc * 64 + j * 16,
                                    acc[i][j], LDOo, wmma::mem_row_major);
    __syncthreads();

    {
        const int row = t >> 3;
        const int l8  = t & 7;
        const int gr  = bm + row;
        float v[64];
        float s = 0.0f, s2 = 0.0f;
        #pragma unroll
        for (int u = 0; u < 16; u++) {
            const int c = l8 * 4 + u * 32;
            float4 a4 = *(float4*)&sf[row * LDOo + c];
            float4 b4 = *(const float4*)&out_b[c];
            float4 x4 = *(const float4*)&x[(size_t)gr * Dsz + c];
            a4.x += b4.x + x4.x; a4.y += b4.y + x4.y;
            a4.z += b4.z + x4.z; a4.w += b4.w + x4.w;
            v[u*4+0] = a4.x; v[u*4+1] = a4.y; v[u*4+2] = a4.z; v[u*4+3] = a4.w;
            s  += a4.x + a4.y + a4.z + a4.w;
            s2 += a4.x*a4.x + a4.y*a4.y + a4.z*a4.z + a4.w*a4.w;
        }
        #pragma unroll
        for (int o = 1; o < 8; o <<= 1) {
            s  += __shfl_xor_sync(0xffffffffu, s,  o);
            s2 += __shfl_xor_sync(0xffffffffu, s2, o);
        }
        const float mu  = s * (1.0f / Dsz);
        const float var = s2 * (1.0f / Dsz) - mu * mu;
        const float inv = rsqrtf(var + LN_EPS);
        #pragma unroll
        for (int u = 0; u < 16; u++) {
            const int c = l8 * 4 + u * 32;
            float4 w4 = *(const float4*)&lnw[c];
            float4 b4 = *(const float4*)&lnb[c];
            float4 r;
            r.x = (v[u*4+0] - mu) * inv * w4.x + b4.x;
            r.y = (v[u*4+1] - mu) * inv * w4.y + b4.y;
            r.z = (v[u*4+2] - mu) * inv * w4.z + b4.z;
            r.w = (v[u*4+3] - mu) * inv * w4.w + b4.w;
            *(float4*)&out[(size_t)gr * Dsz + c] = r;
        }
    }
}

// ---------------------------------------------------------------------------
// Attention: one block per (b, h). 256 threads (8 warps). 2 CTAs/SM.
// ---------------------------------------------------------------------------
#define ATTN_DYN (2 * 128 * 72 * 2 + 128 * 132 * 4)

__global__ void __launch_bounds__(256, 2)
attn_kernel(const __half* __restrict__ qkv,
            const float* __restrict__ corr,
            const int*   __restrict__ mask,
            const float* __restrict__ bscale,
            __half* __restrict__ og)
{
    extern __shared__ __half smh[];
    __half* sQ = smh;
    __half* sK = smh + 128 * 72;
    float*  sS = (float*)(smh + 2 * 128 * 72);
    __half* sP = (__half*)sS;
    __half* sV = sK;
    __shared__ __align__(16) float sB[128];

    const int bh = blockIdx.x;
    const int b  = bh >> 3;
    const int h  = bh & 7;
    const int t  = threadIdx.x;
    const int wid  = t >> 5;

    const uint32_t qb = (uint32_t)__cvta_generic_to_shared(sQ);
    const uint32_t kb = (uint32_t)__cvta_generic_to_shared(sK);
    const __half* src = qkv + (size_t)(b * Lsz) * (3 * Dsz) + h * HDsz;

    #pragma unroll
    for (int i = 0; i < 4; i++) {
        const int j = i * 256 + t;
        const int row = j >> 3, c = j & 7;
        cp16(qb + row * 144 + c * 16, src + (size_t)row * 1536 + c * 8);
        cp16(kb + row * 144 + c * 16, src + (size_t)row * 1536 + 512 + c * 8);
    }
    asm volatile("cp.async.commit_group;");
    if (t < 128) {
        const float bsc = bscale[0];
        sB[t] = mask[b * Lsz + t] ? -1e30f : bsc * corr[b * Lsz + t];
    }
    asm volatile("cp.async.wait_group 0;");
    __syncthreads();

    {
        const int wr = wid & 3, wc = wid >> 2;
        const int r0 = wr * 32, c0 = wc * 64;
        wmma::fragment<wmma::accumulator, 16, 16, 16, float> acc[2][4];
        #pragma unroll
        for (int i = 0; i < 2; i++)
            #pragma unroll
            for (int j = 0; j < 4; j++) wmma::fill_fragment(acc[i][j], 0.0f);

        #pragma unroll
        for (int kk = 0; kk < 64; kk += 16) {
            wmma::fragment<wmma::matrix_a, 16, 16, 16, __half, wmma::row_major> af[2];
            wmma::load_matrix_sync(af[0], &sQ[(r0 +  0) * 72 + kk], 72);
            wmma::load_matrix_sync(af[1], &sQ[(r0 + 16) * 72 + kk], 72);
            #pragma unroll
            for (int j = 0; j < 4; j++) {
                wmma::fragment<wmma::matrix_b, 16, 16, 16, __half, wmma::col_major> bf;
                wmma::load_matrix_sync(bf, &sK[(c0 + j * 16) * 72 + kk], 72);
                wmma::mma_sync(acc[0][j], af[0], bf, acc[0][j]);
                wmma::mma_sync(acc[1][j], af[1], bf, acc[1][j]);
            }
        }
        #pragma unroll
        for (int i = 0; i < 2; i++)
            #pragma unroll
            for (int j = 0; j < 4; j++)
                wmma::store_matrix_sync(&sS[(r0 + i * 16) * 132 + c0 + j * 16],
                                        acc[i][j], 132, wmma::mem_row_major);
    }
    __syncthreads();

    #pragma unroll
    for (int i = 0; i < 4; i++) {
        const int j = i * 256 + t;
        const int row = j >> 3, c = j & 7;
        cp16(kb + row * 144 + c * 16, src + (size_t)row * 1536 + 1024 + c * 8);
    }
    asm volatile("cp.async.commit_group;");

    {
        const int r   = t >> 1;
        const int seg = t & 1;
        const float* srow = &sS[r * 132 + seg * 64];
        const float* brow = &sB[seg * 64];
        float v[64];
        float m = -1e30f;
        #pragma unroll
        for (int u = 0; u < 16; u++) {
            float4 s4 = *(const float4*)(srow + u * 4);
            float4 b4 = *(const float4*)(brow + u * 4);
            v[u*4+0] = fmaf(s4.x, 0.125f, b4.x);
            v[u*4+1] = fmaf(s4.y, 0.125f, b4.y);
            v[u*4+2] = fmaf(s4.z, 0.125f, b4.z);
            v[u*4+3] = fmaf(s4.w, 0.125f, b4.w);
            m = fmaxf(m, fmaxf(fmaxf(v[u*4], v[u*4+1]), fmaxf(v[u*4+2], v[u*4+3])));
        }
        m = fmaxf(m, __shfl_xor_sync(0xffffffffu, m, 1));
        float s = 0.0f;
        #pragma unroll
        for (int u = 0; u < 64; u++) { v[u] = __expf(v[u] - m); s += v[u]; }
        s += __shfl_xor_sync(0xffffffffu, s, 1);
        const float inv = 1.0f / s;
        __half* prow = sP + r * 264 + seg * 64;
        #pragma unroll
        for (int u = 0; u < 8; u++) {
            __half2 p0 = __floats2half2_rn(v[u*8+0] * inv, v[u*8+1] * inv);
            __half2 p1 = __floats2half2_rn(v[u*8+2] * inv, v[u*8+3] * inv);
            __half2 p2 = __floats2half2_rn(v[u*8+4] * inv, v[u*8+5] * inv);
            __half2 p3 = __floats2half2_rn(v[u*8+6] * inv, v[u*8+7] * inv);
            uint4 pk;
            pk.x = *(uint32_t*)&p0; pk.y = *(uint32_t*)&p1;
            pk.z = *(uint32_t*)&p2; pk.w = *(uint32_t*)&p3;
            *(uint4*)(prow + u * 8) = pk;
        }
    }
    asm volatile("cp.async.wait_group 0;");
    __syncthreads();

    {
        const int r0 = wid * 16;
        wmma::fragment<wmma::accumulator, 16, 16, 16, float> acc[4];
        #pragma unroll
        for (int c = 0; c < 4; c++) wmma::fill_fragment(acc[c], 0.0f);

        #pragma unroll
        for (int j = 0; j < 128; j += 16) {
            wmma::fragment<wmma::matrix_a, 16, 16, 16, __half, wmma::row_major> af;
            wmma::load_matrix_sync(af, &sP[r0 * 264 + j], 264);
            #pragma unroll
            for (int c = 0; c < 4; c++) {
                wmma::fragment<wmma::matrix_b, 16, 16, 16, __half, wmma::row_major> bf;
                wmma::load_matrix_sync(bf, &sV[j * 72 + c * 16], 72);
                wmma::mma_sync(acc[c], af, bf, acc[c]);
            }
        }
        #pragma unroll
        for (int c = 0; c < 4; c++)
            wmma::store_matrix_sync(&sS[r0 * 132 + c * 16], acc[c], 132, wmma::mem_row_major);
    }
    __syncthreads();

    {
        const int r   = t >> 1;
        const int seg = (t & 1) * 32;
        __half* dst = og + (size_t)(b * Lsz + r) * Dsz + h * HDsz + seg;
        const float* srcO = &sS[r * 132 + seg];
        #pragma unroll
        for (int u = 0; u < 4; u++) {
            float4 a = *(const float4*)(srcO + u * 8);
            float4 c = *(const float4*)(srcO + u * 8 + 4);
            __half2 h0 = __floats2half2_rn(a.x, a.y);
            __half2 h1 = __floats2half2_rn(a.z, a.w);
            __half2 h2 = __floats2half2_rn(c.x, c.y);
            __half2 h3 = __floats2half2_rn(c.z, c.w);
            uint4 pk;
            pk.x = *(uint32_t*)&h0; pk.y = *(uint32_t*)&h1;
            pk.z = *(uint32_t*)&h2; pk.w = *(uint32_t*)&h3;
            *(uint4*)(dst + u * 8) = pk;
        }
    }
}

// ---------------------------------------------------------------------------
extern "C" void kernel_launch(void* const* d_in, const int* in_sizes, int n_in,
                              void* d_out, int out_size)
{
    const float* x      = (const float*)d_in[0];
    const float* corr   = (const float*)d_in[1];
    const int*   mask   = (const int*)  d_in[2];
    const float* in_w   = (const float*)d_in[3];
    const float* in_b   = (const float*)d_in[4];
    const float* out_w  = (const float*)d_in[5];
    const float* out_b  = (const float*)d_in[6];
    const float* ln_w   = (const float*)d_in[7];
    const float* ln_b   = (const float*)d_in[8];
    const float* bscale = (const float*)d_in[9];
    float* out = (float*)d_out;

    __half *qkv, *oh, *xh, *wih, *woh;
    cudaGetSymbolAddress((void**)&qkv, g_qkv);
    cudaGetSymbolAddress((void**)&oh,  g_oh);
    cudaGetSymbolAddress((void**)&xh,  g_xh);
    cudaGetSymbolAddress((void**)&wih, g_wih);
    cudaGetSymbolAddress((void**)&woh, g_woh);

    const int M = Bsz * Lsz;   // 65536

    cudaFuncSetAttribute((void*)gemm_qkv,    cudaFuncAttributeMaxDynamicSharedMemorySize, GEMM_SMEM);
    cudaFuncSetAttribute((void*)outproj_ln,  cudaFuncAttributeMaxDynamicSharedMemorySize, OPLN_SMEM);
    cudaFuncSetAttribute((void*)attn_kernel, cudaFuncAttributeMaxDynamicSharedMemorySize, ATTN_DYN);

    // 0) fp32 -> fp16 conversions (one launch)
    f2h_multi<<<16896, 256>>>(x, xh, in_w, wih, out_w, woh);

    // 1) QKV projection -> fp16 qkv (R8 config)
    gemm_qkv<<<dim3(3 * Dsz / 128, M / 128), 256, GEMM_SMEM>>>(
        xh, wih, in_b, qkv, M, 3 * Dsz, Dsz);

    // 2) Attention per (b, h)
    attn_kernel<<<Bsz * Hn, 256, ATTN_DYN>>>(qkv, corr, mask, bscale, oh);

    // 3) out_proj + bias + residual + LayerNorm -> out
    outproj_ln<<<M / 64, 512, OPLN_SMEM>>>(oh, woh, out_b, x, ln_w, ln_b, out);
}